// round 1
// baseline (speedup 1.0000x reference)
#include <cuda_runtime.h>
#include <math.h>

#define B_ 256
#define S_ 512
#define V_ 32000
#define E_ 1024
#define H_ 1024
#define O_ 512

// Scratch: xp in [S, B, H] layout so each timestep reads a contiguous [B,H] slab.
__device__ float g_xp[S_ * B_ * H_];     // 512 MB
__device__ float g_h[2][B_ * H_];        // double-buffered hidden state

// ---------------------------------------------------------------------------
// Kernel 1: fused embedding gather + input projection
//   xp[s*B + b, h] = sum_e emb[x[b,s], e] * W_ih[h, e] + b_ih[h]
// Classic 128x128 tile SGEMM (NT: both operands K-contiguous), 256 thr, 8x8/thr.
// ---------------------------------------------------------------------------
__global__ __launch_bounds__(256) void embed_proj_kernel(
    const int* __restrict__ x, const float* __restrict__ emb,
    const float* __restrict__ W_ih, const float* __restrict__ b_ih)
{
    __shared__ float As[16][132];
    __shared__ float Bs[16][132];
    __shared__ int tok_s[128];

    const int tid  = threadIdx.x;
    const int brow = blockIdx.y;   // over BS/128
    const int bcol = blockIdx.x;   // over H/128

    if (tid < 128) {
        int r = brow * 128 + tid;      // r = s*B + b
        int s = r / B_;
        int b = r % B_;
        tok_s[tid] = x[b * S_ + s];
    }
    __syncthreads();

    const int ty = tid >> 4;   // 0..15
    const int tx = tid & 15;   // 0..15

    float acc[8][8];
#pragma unroll
    for (int i = 0; i < 8; i++)
#pragma unroll
        for (int j = 0; j < 8; j++) acc[i][j] = 0.f;

    for (int k0 = 0; k0 < E_; k0 += 16) {
#pragma unroll
        for (int l = 0; l < 2; l++) {
            int vid = tid + l * 256;
            int m = vid >> 2;          // 0..127
            int q = vid & 3;           // 0..3 (16B chunk along K)
            float4 a = *(const float4*)(emb + (size_t)tok_s[m] * E_ + k0 + q * 4);
            As[q * 4 + 0][m] = a.x; As[q * 4 + 1][m] = a.y;
            As[q * 4 + 2][m] = a.z; As[q * 4 + 3][m] = a.w;
            float4 w = *(const float4*)(W_ih + (size_t)(bcol * 128 + m) * E_ + k0 + q * 4);
            Bs[q * 4 + 0][m] = w.x; Bs[q * 4 + 1][m] = w.y;
            Bs[q * 4 + 2][m] = w.z; Bs[q * 4 + 3][m] = w.w;
        }
        __syncthreads();

#pragma unroll
        for (int kk = 0; kk < 16; kk++) {
            float ra[8], rb[8];
#pragma unroll
            for (int i = 0; i < 8; i++) ra[i] = As[kk][ty * 8 + i];
#pragma unroll
            for (int j = 0; j < 8; j++) rb[j] = Bs[kk][tx * 8 + j];
#pragma unroll
            for (int i = 0; i < 8; i++)
#pragma unroll
                for (int j = 0; j < 8; j++) acc[i][j] += ra[i] * rb[j];
        }
        __syncthreads();
    }

#pragma unroll
    for (int i = 0; i < 8; i++) {
        int r = brow * 128 + ty * 8 + i;
        float* dst = g_xp + (size_t)r * H_ + bcol * 128 + tx * 8;
        int colb = bcol * 128 + tx * 8;
#pragma unroll
        for (int j = 0; j < 8; j++)
            dst[j] = acc[i][j] + b_ih[colb + j];
    }
}

// ---------------------------------------------------------------------------
// Kernel 2/3: generic small NT GEMM  C = act(A @ W^T + bias [+ D])
//   A: [M, K]  W: [N, K]  D,C: [M, N]    (K = 1024)
// Tiles 32x64, BK=16, 256 threads, 4x2 per thread.
// ---------------------------------------------------------------------------
template <bool TANH, bool ADD_D>
__global__ __launch_bounds__(256) void gemm_nt_small(
    const float* __restrict__ A, const float* __restrict__ W,
    const float* __restrict__ bias, const float* __restrict__ D,
    float* __restrict__ C, int N, int K)
{
    __shared__ float As[16][36];
    __shared__ float Bs[16][68];

    const int tid = threadIdx.x;
    const int rowBase = blockIdx.y * 32;
    const int colBase = blockIdx.x * 64;

    const int tr = tid >> 5;   // 0..7  (row group, 4 rows each)
    const int tc = tid & 31;   // 0..31 (col group, 2 cols each)

    float acc[4][2];
#pragma unroll
    for (int i = 0; i < 4; i++) { acc[i][0] = 0.f; acc[i][1] = 0.f; }

    for (int k0 = 0; k0 < K; k0 += 16) {
        if (tid < 128) {
            int m = tid >> 2, q = tid & 3;
            float4 a = *(const float4*)(A + (size_t)(rowBase + m) * K + k0 + q * 4);
            As[q * 4 + 0][m] = a.x; As[q * 4 + 1][m] = a.y;
            As[q * 4 + 2][m] = a.z; As[q * 4 + 3][m] = a.w;
        }
        {
            int n = tid >> 2, q = tid & 3;
            float4 w = *(const float4*)(W + (size_t)(colBase + n) * K + k0 + q * 4);
            Bs[q * 4 + 0][n] = w.x; Bs[q * 4 + 1][n] = w.y;
            Bs[q * 4 + 2][n] = w.z; Bs[q * 4 + 3][n] = w.w;
        }
        __syncthreads();

#pragma unroll
        for (int kk = 0; kk < 16; kk++) {
            float ra[4], rb[2];
#pragma unroll
            for (int i = 0; i < 4; i++) ra[i] = As[kk][tr * 4 + i];
            rb[0] = Bs[kk][tc * 2 + 0];
            rb[1] = Bs[kk][tc * 2 + 1];
#pragma unroll
            for (int i = 0; i < 4; i++) {
                acc[i][0] += ra[i] * rb[0];
                acc[i][1] += ra[i] * rb[1];
            }
        }
        __syncthreads();
    }

#pragma unroll
    for (int i = 0; i < 4; i++) {
        int row = rowBase + tr * 4 + i;
#pragma unroll
        for (int j = 0; j < 2; j++) {
            int col = colBase + tc * 2 + j;
            float v = acc[i][j] + bias[col];
            if (ADD_D) v += D[(size_t)row * N + col];
            if (TANH) v = tanhf(v);
            C[(size_t)row * N + col] = v;
        }
    }
}

__global__ void zero_h_kernel() {
    int i = blockIdx.x * blockDim.x + threadIdx.x;
    if (i < B_ * H_) g_h[0][i] = 0.f;
}

// ---------------------------------------------------------------------------
extern "C" void kernel_launch(void* const* d_in, const int* in_sizes, int n_in,
                              void* d_out, int out_size)
{
    const int*   x     = (const int*)d_in[0];
    const float* emb   = (const float*)d_in[1];
    const float* W_ih  = (const float*)d_in[2];
    const float* b_ih  = (const float*)d_in[3];
    const float* W_hh  = (const float*)d_in[4];
    const float* b_hh  = (const float*)d_in[5];
    const float* W_clf = (const float*)d_in[6];
    const float* b_clf = (const float*)d_in[7];
    float*       out   = (float*)d_out;

    float* xp = nullptr;
    float* hb = nullptr;
    cudaGetSymbolAddress((void**)&xp, g_xp);
    cudaGetSymbolAddress((void**)&hb, g_h);

    // h0 = 0
    zero_h_kernel<<<(B_ * H_ + 255) / 256, 256>>>();

    // xp[s,b,h] = emb[x[b,s]] @ W_ih^T + b_ih
    embed_proj_kernel<<<dim3(H_ / 128, (B_ * S_) / 128), 256>>>(x, emb, W_ih, b_ih);

    // scan: h_{t+1} = tanh(xp_t + h_t @ W_hh^T + b_hh)
    for (int s = 0; s < S_; s++) {
        const float* hin  = hb + (s & 1) * (B_ * H_);
        float*       hout = hb + ((s + 1) & 1) * (B_ * H_);
        const float* xpt  = xp + (size_t)s * B_ * H_;
        gemm_nt_small<true, true><<<dim3(H_ / 64, B_ / 32), 256>>>(
            hin, W_hh, b_hh, xpt, hout, H_, H_);
    }

    // out = h_final @ W_clf^T + b_clf   (final h lands in buffer 0 after 512 steps)
    gemm_nt_small<false, false><<<dim3(O_ / 64, B_ / 32), 256>>>(
        hb, W_clf, b_clf, nullptr, out, O_, H_);
}

// round 3
// speedup vs baseline: 2.6020x; 2.6020x over previous
#include <cuda_runtime.h>
#include <math.h>
#include <stdint.h>

#define B_ 256
#define S_ 512
#define E_ 1024
#define H_ 1024
#define O_ 512

// ---------------------------------------------------------------------------
// Device scratch
// ---------------------------------------------------------------------------
__device__ float g_xp[S_ * B_ * H_];       // [S,B,H] input projections (512 MB)
__device__ float g_h[2][B_ * H_];          // full-precision h, double buffered
__device__ float g_hsplit[4][B_ * H_];     // plane = buf*2 + part (hi/lo tf32)
__device__ float g_wsplit[2][H_ * H_];     // W_hh split: plane = part (hi/lo)

// ---------------------------------------------------------------------------
// Helpers
// ---------------------------------------------------------------------------
__device__ __forceinline__ uint32_t smem_u32(const void* p) {
    uint32_t a;
    asm("{ .reg .u64 t; cvta.to.shared.u64 t, %1; cvt.u32.u64 %0, t; }" : "=r"(a) : "l"(p));
    return a;
}
__device__ __forceinline__ float tf32_rna(float x) {
    uint32_t u; asm("cvt.rna.tf32.f32 %0, %1;" : "=r"(u) : "f"(x));
    return __uint_as_float(u);
}

#define CP_ASYNC16(dst, src) \
    asm volatile("cp.async.cg.shared.global [%0], [%1], 16;" :: "r"(dst), "l"(src))
#define CP_COMMIT() asm volatile("cp.async.commit_group;" ::: "memory")
#define CP_WAIT0()  asm volatile("cp.async.wait_group 0;" ::: "memory")
#define CP_WAIT1()  asm volatile("cp.async.wait_group 1;" ::: "memory")

// D += A*B   (m16n8k8 tf32, row.col)
__device__ __forceinline__ void mma_tf32(float* c,
    uint32_t a0, uint32_t a1, uint32_t a2, uint32_t a3, uint32_t b0, uint32_t b1)
{
    asm volatile(
        "mma.sync.aligned.m16n8k8.row.col.f32.tf32.tf32.f32 "
        "{%0,%1,%2,%3}, {%4,%5,%6,%7}, {%8,%9}, {%0,%1,%2,%3};"
        : "+f"(c[0]), "+f"(c[1]), "+f"(c[2]), "+f"(c[3])
        : "r"(a0), "r"(a1), "r"(a2), "r"(a3), "r"(b0), "r"(b1));
}

// ---------------------------------------------------------------------------
// Recurrent step: h_out = tanh(h_in @ W_hh^T + xp_t + b_hh) via 3xTF32 mma.sync
// CTA tile M=32, N=64, BK=32.  Grid (16, 8) = 128 CTAs, 128 threads each.
// SMEM (dynamic): 2 stages x { Ahi[32][36], Alo[32][36], Bhi[64][36], Blo[64][36] }
// ---------------------------------------------------------------------------
#define BK 32
#define AP 36                      // padded row stride (floats)
#define A_FLOATS (32 * AP)         // 1152
#define B_FLOATS (64 * AP)         // 2304
#define STAGE_FLOATS (2 * A_FLOATS + 2 * B_FLOATS)   // 6912
#define STEP_SMEM (2 * STAGE_FLOATS * 4)             // 55296 bytes

__device__ __forceinline__ void load_stage(
    uint32_t smBase, int stage,
    const float* __restrict__ ahi, const float* __restrict__ alo,
    const float* __restrict__ whi, const float* __restrict__ wlo,
    int k0, int mbase, int nbase, int tid)
{
    uint32_t s = smBase + stage * (STAGE_FLOATS * 4);
    // A planes: 32 rows x 32 floats = 256 float4 per plane -> 2 per thread
#pragma unroll
    for (int j = 0; j < 2; j++) {
        int idx = tid + j * 128;
        int row = idx >> 3, q = idx & 7;
        uint32_t doff = (row * AP + q * 4) * 4;
        size_t soff = (size_t)(mbase + row) * H_ + k0 + q * 4;
        CP_ASYNC16(s + doff, ahi + soff);
        CP_ASYNC16(s + A_FLOATS * 4 + doff, alo + soff);
    }
    // B planes: 64 rows x 32 floats = 512 float4 per plane -> 4 per thread
#pragma unroll
    for (int j = 0; j < 4; j++) {
        int idx = tid + j * 128;
        int row = idx >> 3, q = idx & 7;
        uint32_t doff = (row * AP + q * 4) * 4;
        size_t soff = (size_t)(nbase + row) * H_ + k0 + q * 4;
        CP_ASYNC16(s + 2 * A_FLOATS * 4 + doff, whi + soff);
        CP_ASYNC16(s + 2 * A_FLOATS * 4 + B_FLOATS * 4 + doff, wlo + soff);
    }
    CP_COMMIT();
}

__global__ __launch_bounds__(128, 1) void rnn_step_kernel(
    const float* __restrict__ ahi, const float* __restrict__ alo,
    const float* __restrict__ whi, const float* __restrict__ wlo,
    const float* __restrict__ xp_t, const float* __restrict__ b_hh,
    float* __restrict__ hf_out, float* __restrict__ hhi_out,
    float* __restrict__ hlo_out)
{
    extern __shared__ float sm[];
    const int tid = threadIdx.x;
    const int wid = tid >> 5;
    const int lane = tid & 31;
    const int g = lane >> 2;       // groupID 0..7
    const int t = lane & 3;        // thread-in-group 0..3

    const int nblk = blockIdx.x;   // 0..15
    const int mblk = blockIdx.y;   // 0..7
    const int mbase = mblk * 32;
    const int nbase = nblk * 64;

    const int wm = (wid & 1) * 16;       // warp row offset in tile
    const int wn = (wid >> 1) * 32;      // warp col offset in tile

    uint32_t smBase = smem_u32(sm);

    float acc[4][4];
#pragma unroll
    for (int i = 0; i < 4; i++)
#pragma unroll
        for (int j = 0; j < 4; j++) acc[i][j] = 0.f;

    load_stage(smBase, 0, ahi, alo, whi, wlo, 0, mbase, nbase, tid);

    const int NIT = H_ / BK;   // 32
    for (int it = 0; it < NIT; it++) {
        int stage = it & 1;
        if (it + 1 < NIT) {
            load_stage(smBase, stage ^ 1, ahi, alo, whi, wlo, (it + 1) * BK,
                       mbase, nbase, tid);
            CP_WAIT1();
        } else {
            CP_WAIT0();
        }
        __syncthreads();

        const float* As_hi = sm + stage * STAGE_FLOATS;
        const float* As_lo = As_hi + A_FLOATS;
        const float* Bs_hi = As_hi + 2 * A_FLOATS;
        const float* Bs_lo = Bs_hi + B_FLOATS;

#pragma unroll
        for (int k8 = 0; k8 < 4; k8++) {
            const int kc = k8 * 8;
            uint32_t ah0 = __float_as_uint(As_hi[(wm + g) * AP + kc + t]);
            uint32_t ah1 = __float_as_uint(As_hi[(wm + g + 8) * AP + kc + t]);
            uint32_t ah2 = __float_as_uint(As_hi[(wm + g) * AP + kc + t + 4]);
            uint32_t ah3 = __float_as_uint(As_hi[(wm + g + 8) * AP + kc + t + 4]);
            uint32_t al0 = __float_as_uint(As_lo[(wm + g) * AP + kc + t]);
            uint32_t al1 = __float_as_uint(As_lo[(wm + g + 8) * AP + kc + t]);
            uint32_t al2 = __float_as_uint(As_lo[(wm + g) * AP + kc + t + 4]);
            uint32_t al3 = __float_as_uint(As_lo[(wm + g + 8) * AP + kc + t + 4]);
#pragma unroll
            for (int nt = 0; nt < 4; nt++) {
                const int nr = wn + nt * 8 + g;
                uint32_t bh0 = __float_as_uint(Bs_hi[nr * AP + kc + t]);
                uint32_t bh1 = __float_as_uint(Bs_hi[nr * AP + kc + t + 4]);
                uint32_t bl0 = __float_as_uint(Bs_lo[nr * AP + kc + t]);
                uint32_t bl1 = __float_as_uint(Bs_lo[nr * AP + kc + t + 4]);
                mma_tf32(acc[nt], ah0, ah1, ah2, ah3, bh0, bh1);
                mma_tf32(acc[nt], ah0, ah1, ah2, ah3, bl0, bl1);
                mma_tf32(acc[nt], al0, al1, al2, al3, bh0, bh1);
            }
        }
        __syncthreads();
    }

    // ---------------- epilogue: + xp + b_hh, tanh, write full + hi/lo ----------
    const int row0 = mbase + wm + g;
    const int row1 = row0 + 8;
#pragma unroll
    for (int nt = 0; nt < 4; nt++) {
        const int col = nbase + wn + nt * 8 + 2 * t;
        float2 bv = *(const float2*)(b_hh + col);
        float2 x0 = *(const float2*)(xp_t + (size_t)row0 * H_ + col);
        float2 x1 = *(const float2*)(xp_t + (size_t)row1 * H_ + col);

        float v0 = tanhf(acc[nt][0] + x0.x + bv.x);
        float v1 = tanhf(acc[nt][1] + x0.y + bv.y);
        float v2 = tanhf(acc[nt][2] + x1.x + bv.x);
        float v3 = tanhf(acc[nt][3] + x1.y + bv.y);

        float h0 = tf32_rna(v0), h1 = tf32_rna(v1);
        float h2 = tf32_rna(v2), h3 = tf32_rna(v3);

        *(float2*)(hf_out + (size_t)row0 * H_ + col) = make_float2(v0, v1);
        *(float2*)(hf_out + (size_t)row1 * H_ + col) = make_float2(v2, v3);
        *(float2*)(hhi_out + (size_t)row0 * H_ + col) = make_float2(h0, h1);
        *(float2*)(hhi_out + (size_t)row1 * H_ + col) = make_float2(h2, h3);
        *(float2*)(hlo_out + (size_t)row0 * H_ + col) =
            make_float2(tf32_rna(v0 - h0), tf32_rna(v1 - h1));
        *(float2*)(hlo_out + (size_t)row1 * H_ + col) =
            make_float2(tf32_rna(v2 - h2), tf32_rna(v3 - h3));
    }
}

// ---------------------------------------------------------------------------
// Kernel 1: fused embedding gather + input projection (scalar SGEMM, unchanged)
// ---------------------------------------------------------------------------
__global__ __launch_bounds__(256) void embed_proj_kernel(
    const int* __restrict__ x, const float* __restrict__ emb,
    const float* __restrict__ W_ih, const float* __restrict__ b_ih)
{
    __shared__ float As[16][132];
    __shared__ float Bs[16][132];
    __shared__ int tok_s[128];

    const int tid  = threadIdx.x;
    const int brow = blockIdx.y;
    const int bcol = blockIdx.x;

    if (tid < 128) {
        int r = brow * 128 + tid;
        int s = r / B_;
        int b = r % B_;
        tok_s[tid] = x[b * S_ + s];
    }
    __syncthreads();

    const int ty = tid >> 4;
    const int tx = tid & 15;

    float acc[8][8];
#pragma unroll
    for (int i = 0; i < 8; i++)
#pragma unroll
        for (int j = 0; j < 8; j++) acc[i][j] = 0.f;

    for (int k0 = 0; k0 < E_; k0 += 16) {
#pragma unroll
        for (int l = 0; l < 2; l++) {
            int vid = tid + l * 256;
            int m = vid >> 2;
            int q = vid & 3;
            float4 a = *(const float4*)(emb + (size_t)tok_s[m] * E_ + k0 + q * 4);
            As[q * 4 + 0][m] = a.x; As[q * 4 + 1][m] = a.y;
            As[q * 4 + 2][m] = a.z; As[q * 4 + 3][m] = a.w;
            float4 w = *(const float4*)(W_ih + (size_t)(bcol * 128 + m) * E_ + k0 + q * 4);
            Bs[q * 4 + 0][m] = w.x; Bs[q * 4 + 1][m] = w.y;
            Bs[q * 4 + 2][m] = w.z; Bs[q * 4 + 3][m] = w.w;
        }
        __syncthreads();

#pragma unroll
        for (int kk = 0; kk < 16; kk++) {
            float ra[8], rb[8];
#pragma unroll
            for (int i = 0; i < 8; i++) ra[i] = As[kk][ty * 8 + i];
#pragma unroll
            for (int j = 0; j < 8; j++) rb[j] = Bs[kk][tx * 8 + j];
#pragma unroll
            for (int i = 0; i < 8; i++)
#pragma unroll
                for (int j = 0; j < 8; j++) acc[i][j] += ra[i] * rb[j];
        }
        __syncthreads();
    }

#pragma unroll
    for (int i = 0; i < 8; i++) {
        int r = brow * 128 + ty * 8 + i;
        float* dst = g_xp + (size_t)r * H_ + bcol * 128 + tx * 8;
        int colb = bcol * 128 + tx * 8;
#pragma unroll
        for (int j = 0; j < 8; j++)
            dst[j] = acc[i][j] + b_ih[colb + j];
    }
}

// ---------------------------------------------------------------------------
// Classifier GEMM (scalar, tiny)
// ---------------------------------------------------------------------------
__global__ __launch_bounds__(256) void gemm_clf(
    const float* __restrict__ A, const float* __restrict__ W,
    const float* __restrict__ bias, float* __restrict__ C, int N, int K)
{
    __shared__ float As[16][36];
    __shared__ float Bs[16][68];

    const int tid = threadIdx.x;
    const int rowBase = blockIdx.y * 32;
    const int colBase = blockIdx.x * 64;
    const int tr = tid >> 5;
    const int tc = tid & 31;

    float acc[4][2];
#pragma unroll
    for (int i = 0; i < 4; i++) { acc[i][0] = 0.f; acc[i][1] = 0.f; }

    for (int k0 = 0; k0 < K; k0 += 16) {
        if (tid < 128) {
            int m = tid >> 2, q = tid & 3;
            float4 a = *(const float4*)(A + (size_t)(rowBase + m) * K + k0 + q * 4);
            As[q * 4 + 0][m] = a.x; As[q * 4 + 1][m] = a.y;
            As[q * 4 + 2][m] = a.z; As[q * 4 + 3][m] = a.w;
        }
        {
            int n = tid >> 2, q = tid & 3;
            float4 w = *(const float4*)(W + (size_t)(colBase + n) * K + k0 + q * 4);
            Bs[q * 4 + 0][n] = w.x; Bs[q * 4 + 1][n] = w.y;
            Bs[q * 4 + 2][n] = w.z; Bs[q * 4 + 3][n] = w.w;
        }
        __syncthreads();

#pragma unroll
        for (int kk = 0; kk < 16; kk++) {
            float ra[4], rb[2];
#pragma unroll
            for (int i = 0; i < 4; i++) ra[i] = As[kk][tr * 4 + i];
            rb[0] = Bs[kk][tc * 2 + 0];
            rb[1] = Bs[kk][tc * 2 + 1];
#pragma unroll
            for (int i = 0; i < 4; i++) {
                acc[i][0] += ra[i] * rb[0];
                acc[i][1] += ra[i] * rb[1];
            }
        }
        __syncthreads();
    }

#pragma unroll
    for (int i = 0; i < 4; i++) {
        int row = rowBase + tr * 4 + i;
#pragma unroll
        for (int j = 0; j < 2; j++) {
            int col = colBase + tc * 2 + j;
            C[(size_t)row * N + col] = acc[i][j] + bias[col];
        }
    }
}

// ---------------------------------------------------------------------------
// Init kernels
// ---------------------------------------------------------------------------
__global__ void zero_h_kernel() {
    int i = blockIdx.x * blockDim.x + threadIdx.x;
    if (i < B_ * H_) {
        g_h[0][i] = 0.f;
        g_hsplit[0][i] = 0.f;
        g_hsplit[1][i] = 0.f;
    }
}

__global__ void wsplit_kernel(const float* __restrict__ W) {
    int i = blockIdx.x * blockDim.x + threadIdx.x;
    if (i < H_ * H_) {
        float w = W[i];
        float hi = tf32_rna(w);
        g_wsplit[0][i] = hi;
        g_wsplit[1][i] = tf32_rna(w - hi);
    }
}

// ---------------------------------------------------------------------------
extern "C" void kernel_launch(void* const* d_in, const int* in_sizes, int n_in,
                              void* d_out, int out_size)
{
    const int*   x     = (const int*)d_in[0];
    const float* emb   = (const float*)d_in[1];
    const float* W_ih  = (const float*)d_in[2];
    const float* b_ih  = (const float*)d_in[3];
    const float* W_hh  = (const float*)d_in[4];
    const float* b_hh  = (const float*)d_in[5];
    const float* W_clf = (const float*)d_in[6];
    const float* b_clf = (const float*)d_in[7];
    float*       out   = (float*)d_out;

    float *xp = nullptr, *hb = nullptr, *hs = nullptr, *ws = nullptr;
    cudaGetSymbolAddress((void**)&xp, g_xp);
    cudaGetSymbolAddress((void**)&hb, g_h);
    cudaGetSymbolAddress((void**)&hs, g_hsplit);
    cudaGetSymbolAddress((void**)&ws, g_wsplit);

    static bool attrSet = false;
    if (!attrSet) {
        cudaFuncSetAttribute(rnn_step_kernel,
                             cudaFuncAttributeMaxDynamicSharedMemorySize, STEP_SMEM);
        attrSet = true;
    }

    // --- init: h0 = 0, split W_hh into hi/lo tf32 planes ---
    zero_h_kernel<<<(B_ * H_ + 255) / 256, 256>>>();
    wsplit_kernel<<<(H_ * H_ + 255) / 256, 256>>>(W_hh);

    // --- xp[s,b,h] = emb[x[b,s]] @ W_ih^T + b_ih ---
    embed_proj_kernel<<<dim3(H_ / 128, (B_ * S_) / 128), 256>>>(x, emb, W_ih, b_ih);

    // --- scan: h_{t+1} = tanh(h_t @ W_hh^T + xp_t + b_hh) ---
    const float* whi = ws;
    const float* wlo = ws + (size_t)H_ * H_;
    for (int s = 0; s < S_; s++) {
        int in_buf = s & 1;
        int out_buf = (s + 1) & 1;
        const float* xpt = xp + (size_t)s * B_ * H_;
        rnn_step_kernel<<<dim3(H_ / 64, B_ / 32), 128, STEP_SMEM>>>(
            hs + (size_t)(in_buf * 2) * B_ * H_,
            hs + (size_t)(in_buf * 2 + 1) * B_ * H_,
            whi, wlo, xpt, b_hh,
            hb + (size_t)out_buf * B_ * H_,
            hs + (size_t)(out_buf * 2) * B_ * H_,
            hs + (size_t)(out_buf * 2 + 1) * B_ * H_);
    }

    // --- classifier: out = h_final @ W_clf^T + b_clf (final in buffer 0) ---
    gemm_clf<<<dim3(O_ / 64, B_ / 32), 256>>>(hb, W_clf, b_clf, out, O_, H_);
}

// round 4
// speedup vs baseline: 2.6893x; 1.0336x over previous
#include <cuda_runtime.h>
#include <math.h>
#include <stdint.h>

#define B_ 256
#define S_ 512
#define E_ 1024
#define H_ 1024
#define O_ 512

// ---------------------------------------------------------------------------
// Device scratch
// NOTE: g_hsplit / g_wsplit planes are stored with a k-pair PERMUTATION along
// their last (H) dim: within each 8-col block, orig col j is stored at
// pos = ((j&3)<<1) | (j>>2).  This makes the mma fragment pairs (t, t+4)
// adjacent so the step kernel can use LDS.64.
// ---------------------------------------------------------------------------
__device__ float g_xp[S_ * B_ * H_];       // [S,B,H] input projections (plain)
__device__ float g_h[2][B_ * H_];          // full-precision h (plain layout)
__device__ float g_hsplit[4][B_ * H_];     // plane = buf*2 + part (hi/lo tf32, permuted)
__device__ float g_wsplit[2][H_ * H_];     // W_hh split hi/lo (permuted cols)

// ---------------------------------------------------------------------------
// Helpers
// ---------------------------------------------------------------------------
__device__ __forceinline__ uint32_t smem_u32(const void* p) {
    uint32_t a;
    asm("{ .reg .u64 t; cvta.to.shared.u64 t, %1; cvt.u32.u64 %0, t; }" : "=r"(a) : "l"(p));
    return a;
}
__device__ __forceinline__ float tf32_rna(float x) {
    uint32_t u; asm("cvt.rna.tf32.f32 %0, %1;" : "=r"(u) : "f"(x));
    return __uint_as_float(u);
}

#define CP_ASYNC16(dst, src) \
    asm volatile("cp.async.cg.shared.global [%0], [%1], 16;" :: "r"(dst), "l"(src))
#define CP_COMMIT() asm volatile("cp.async.commit_group;" ::: "memory")
#define CP_WAIT0()  asm volatile("cp.async.wait_group 0;" ::: "memory")
#define CP_WAIT1()  asm volatile("cp.async.wait_group 1;" ::: "memory")
#define CP_WAIT2()  asm volatile("cp.async.wait_group 2;" ::: "memory")

// D += A*B   (m16n8k8 tf32, row.col)
__device__ __forceinline__ void mma_tf32(float* c,
    uint32_t a0, uint32_t a1, uint32_t a2, uint32_t a3, uint32_t b0, uint32_t b1)
{
    asm volatile(
        "mma.sync.aligned.m16n8k8.row.col.f32.tf32.tf32.f32 "
        "{%0,%1,%2,%3}, {%4,%5,%6,%7}, {%8,%9}, {%0,%1,%2,%3};"
        : "+f"(c[0]), "+f"(c[1]), "+f"(c[2]), "+f"(c[3])
        : "r"(a0), "r"(a1), "r"(a2), "r"(a3), "r"(b0), "r"(b1));
}

// ---------------------------------------------------------------------------
// Recurrent step: h_out = tanh(h_in @ W_hh^T + xp_t + b_hh) via 3xTF32 mma.sync
// CTA tile M=32, N=64.  Grid (16, 8) = 128 CTAs, 256 threads (8 warps).
// Warp = (nslot in 2) x (kgrp in 4), warp tile m32 x n32 over K/4 = 256.
// 3-stage cp.async pipeline, BK=64 per stage.  XOR-swizzled smem, LDS.64 frags.
// ---------------------------------------------------------------------------
#define BK 64
#define A_PL (32 * 64)                  // floats per A plane per stage (2048)
#define B_PL (64 * 64)                  // floats per B plane per stage (4096)
#define STAGE_FLOATS (2 * A_PL + 2 * B_PL)   // 12288
#define NSTAGE 3
#define STEP_SMEM (NSTAGE * STAGE_FLOATS * 4)  // 147456 bytes
#define NIT (H_ / BK)                   // 16

// swizzled float index within a plane (row-major, 64 floats/row, 16B-chunk XOR)
__device__ __forceinline__ int swf(int row, int col) {
    return (row << 6) + ((((col >> 2) ^ (row & 7))) << 2) + (col & 3);
}

__device__ __forceinline__ void load_stage(
    uint32_t smBase, int stage,
    const float* __restrict__ ahi, const float* __restrict__ alo,
    const float* __restrict__ whi, const float* __restrict__ wlo,
    int k0, int mbase, int nbase, int tid)
{
    uint32_t s = smBase + stage * (STAGE_FLOATS * 4);
    // A planes: 32 rows x 16 chunks = 512 chunks -> 2 per thread
#pragma unroll
    for (int j = 0; j < 2; j++) {
        int idx = tid + j * 256;
        int row = idx >> 4, q = idx & 15;
        int qs = q ^ (row & 7);
        uint32_t doff = ((row << 6) + (qs << 2)) * 4;
        size_t soff = (size_t)(mbase + row) * H_ + k0 + q * 4;
        CP_ASYNC16(s + doff, ahi + soff);
        CP_ASYNC16(s + A_PL * 4 + doff, alo + soff);
    }
    // B planes: 64 rows x 16 chunks = 1024 chunks -> 4 per thread
#pragma unroll
    for (int j = 0; j < 4; j++) {
        int idx = tid + j * 256;
        int row = idx >> 4, q = idx & 15;
        int qs = q ^ (row & 7);
        uint32_t doff = ((row << 6) + (qs << 2)) * 4;
        size_t soff = (size_t)(nbase + row) * H_ + k0 + q * 4;
        CP_ASYNC16(s + 2 * A_PL * 4 + doff, whi + soff);
        CP_ASYNC16(s + 2 * A_PL * 4 + B_PL * 4 + doff, wlo + soff);
    }
    CP_COMMIT();
}

__global__ __launch_bounds__(256, 1) void rnn_step_kernel(
    const float* __restrict__ ahi, const float* __restrict__ alo,
    const float* __restrict__ whi, const float* __restrict__ wlo,
    const float* __restrict__ xp_t, const float* __restrict__ b_hh,
    float* __restrict__ hf_out, float* __restrict__ hhi_out,
    float* __restrict__ hlo_out)
{
    extern __shared__ float sm[];
    const int tid = threadIdx.x;
    const int wid = tid >> 5;
    const int lane = tid & 31;
    const int g = lane >> 2;       // groupID 0..7
    const int t = lane & 3;        // 0..3

    const int nslot = wid & 1;     // n half of CTA tile
    const int kgrp = wid >> 1;     // 0..3, K split

    const int nblk = blockIdx.x;   // 0..15
    const int mblk = blockIdx.y;   // 0..7
    const int mbase = mblk * 32;
    const int nbase = nblk * 64;
    const int nb0 = nslot * 32;

    uint32_t smBase = smem_u32(sm);

    float acc[2][4][4];
#pragma unroll
    for (int mt = 0; mt < 2; mt++)
#pragma unroll
        for (int nt = 0; nt < 4; nt++)
#pragma unroll
            for (int i = 0; i < 4; i++) acc[mt][nt][i] = 0.f;

    load_stage(smBase, 0, ahi, alo, whi, wlo, 0, mbase, nbase, tid);
    load_stage(smBase, 1, ahi, alo, whi, wlo, BK, mbase, nbase, tid);

    for (int it = 0; it < NIT; it++) {
        int stage = it % NSTAGE;
        if (it + 2 < NIT) {
            load_stage(smBase, (it + 2) % NSTAGE, ahi, alo, whi, wlo,
                       (it + 2) * BK, mbase, nbase, tid);
            CP_WAIT2();
        } else if (it + 1 < NIT) {
            CP_WAIT1();
        } else {
            CP_WAIT0();
        }
        __syncthreads();

        const float* Ah = sm + stage * STAGE_FLOATS;
        const float* Al = Ah + A_PL;
        const float* Bh = Ah + 2 * A_PL;
        const float* Bl = Bh + B_PL;

#pragma unroll
        for (int k8 = 0; k8 < 2; k8++) {
            const int kc = kgrp * 16 + k8 * 8;
            const int col = kc + 2 * t;
            // A fragments: rows mt*16 + rp*8 + g, pairs (a0,a2)/(a1,a3) via float2
            float2 fh[4], fl[4];
#pragma unroll
            for (int mt = 0; mt < 2; mt++)
#pragma unroll
                for (int rp = 0; rp < 2; rp++) {
                    int r = mt * 16 + rp * 8 + g;
                    fh[mt * 2 + rp] = *(const float2*)&Ah[swf(r, col)];
                    fl[mt * 2 + rp] = *(const float2*)&Al[swf(r, col)];
                }
#pragma unroll
            for (int nt = 0; nt < 4; nt++) {
                int nr = nb0 + nt * 8 + g;
                float2 bh = *(const float2*)&Bh[swf(nr, col)];
                float2 bl = *(const float2*)&Bl[swf(nr, col)];
                uint32_t bh0 = __float_as_uint(bh.x), bh1 = __float_as_uint(bh.y);
                uint32_t bl0 = __float_as_uint(bl.x), bl1 = __float_as_uint(bl.y);
#pragma unroll
                for (int mt = 0; mt < 2; mt++) {
                    uint32_t a0 = __float_as_uint(fh[mt * 2].x);
                    uint32_t a1 = __float_as_uint(fh[mt * 2 + 1].x);
                    uint32_t a2 = __float_as_uint(fh[mt * 2].y);
                    uint32_t a3 = __float_as_uint(fh[mt * 2 + 1].y);
                    uint32_t l0 = __float_as_uint(fl[mt * 2].x);
                    uint32_t l1 = __float_as_uint(fl[mt * 2 + 1].x);
                    uint32_t l2 = __float_as_uint(fl[mt * 2].y);
                    uint32_t l3 = __float_as_uint(fl[mt * 2 + 1].y);
                    mma_tf32(acc[mt][nt], a0, a1, a2, a3, bh0, bh1);
                    mma_tf32(acc[mt][nt], a0, a1, a2, a3, bl0, bl1);
                    mma_tf32(acc[mt][nt], l0, l1, l2, l3, bh0, bh1);
                }
            }
        }
        __syncthreads();
    }

    // ---------------- K-split reduction through smem ----------------
    float* red = sm;   // all cp.async drained; stages reusable
    if (kgrp > 0) {
        int base = ((kgrp - 1) * 2 + nslot) * 1024 + lane * 32;
#pragma unroll
        for (int ch = 0; ch < 8; ch++) {
            int mt = ch >> 2, nt = ch & 3;
            int chs = ch ^ (lane & 7);
            *(float4*)&red[base + chs * 4] = *(const float4*)acc[mt][nt];
        }
    }
    __syncthreads();
    if (kgrp == 0) {
#pragma unroll
        for (int k = 1; k < 4; k++) {
            int base = ((k - 1) * 2 + nslot) * 1024 + lane * 32;
#pragma unroll
            for (int ch = 0; ch < 8; ch++) {
                int mt = ch >> 2, nt = ch & 3;
                int chs = ch ^ (lane & 7);
                float4 v = *(const float4*)&red[base + chs * 4];
                acc[mt][nt][0] += v.x; acc[mt][nt][1] += v.y;
                acc[mt][nt][2] += v.z; acc[mt][nt][3] += v.w;
            }
        }

        // ---------------- epilogue: + xp + b_hh, tanh, store planes ----------
#pragma unroll
        for (int mt = 0; mt < 2; mt++) {
            const int row0 = mbase + mt * 16 + g;
            const int row1 = row0 + 8;
#pragma unroll
            for (int nt = 0; nt < 4; nt++) {
                const int jb = nbase + nb0 + nt * 8;
                const int col = jb + 2 * t;
                float2 bv = *(const float2*)(b_hh + col);
                float2 x0 = *(const float2*)(xp_t + (size_t)row0 * H_ + col);
                float2 x1 = *(const float2*)(xp_t + (size_t)row1 * H_ + col);

                float v0 = tanhf(acc[mt][nt][0] + x0.x + bv.x);
                float v1 = tanhf(acc[mt][nt][1] + x0.y + bv.y);
                float v2 = tanhf(acc[mt][nt][2] + x1.x + bv.x);
                float v3 = tanhf(acc[mt][nt][3] + x1.y + bv.y);

                float h0 = tf32_rna(v0), h1 = tf32_rna(v1);
                float h2 = tf32_rna(v2), h3 = tf32_rna(v3);

                // plain layout for classifier / debugging
                *(float2*)(hf_out + (size_t)row0 * H_ + col) = make_float2(v0, v1);
                *(float2*)(hf_out + (size_t)row1 * H_ + col) = make_float2(v2, v3);

                // permuted positions for next step's MMA operands
                const int p0 = jb + (((2 * t) & 3) << 1) + (t >> 1);
                const int p1 = jb + (((2 * t + 1) & 3) << 1) + (t >> 1);
                hhi_out[(size_t)row0 * H_ + p0] = h0;
                hhi_out[(size_t)row0 * H_ + p1] = h1;
                hhi_out[(size_t)row1 * H_ + p0] = h2;
                hhi_out[(size_t)row1 * H_ + p1] = h3;
                hlo_out[(size_t)row0 * H_ + p0] = tf32_rna(v0 - h0);
                hlo_out[(size_t)row0 * H_ + p1] = tf32_rna(v1 - h1);
                hlo_out[(size_t)row1 * H_ + p0] = tf32_rna(v2 - h2);
                hlo_out[(size_t)row1 * H_ + p1] = tf32_rna(v3 - h3);
            }
        }
    }
}

// ---------------------------------------------------------------------------
// Kernel 1: fused embedding gather + input projection (scalar SGEMM)
// ---------------------------------------------------------------------------
__global__ __launch_bounds__(256) void embed_proj_kernel(
    const int* __restrict__ x, const float* __restrict__ emb,
    const float* __restrict__ W_ih, const float* __restrict__ b_ih)
{
    __shared__ float As[16][132];
    __shared__ float Bs[16][132];
    __shared__ int tok_s[128];

    const int tid  = threadIdx.x;
    const int brow = blockIdx.y;
    const int bcol = blockIdx.x;

    if (tid < 128) {
        int r = brow * 128 + tid;
        int s = r / B_;
        int b = r % B_;
        tok_s[tid] = x[b * S_ + s];
    }
    __syncthreads();

    const int ty = tid >> 4;
    const int tx = tid & 15;

    float acc[8][8];
#pragma unroll
    for (int i = 0; i < 8; i++)
#pragma unroll
        for (int j = 0; j < 8; j++) acc[i][j] = 0.f;

    for (int k0 = 0; k0 < E_; k0 += 16) {
#pragma unroll
        for (int l = 0; l < 2; l++) {
            int vid = tid + l * 256;
            int m = vid >> 2;
            int q = vid & 3;
            float4 a = *(const float4*)(emb + (size_t)tok_s[m] * E_ + k0 + q * 4);
            As[q * 4 + 0][m] = a.x; As[q * 4 + 1][m] = a.y;
            As[q * 4 + 2][m] = a.z; As[q * 4 + 3][m] = a.w;
            float4 w = *(const float4*)(W_ih + (size_t)(bcol * 128 + m) * E_ + k0 + q * 4);
            Bs[q * 4 + 0][m] = w.x; Bs[q * 4 + 1][m] = w.y;
            Bs[q * 4 + 2][m] = w.z; Bs[q * 4 + 3][m] = w.w;
        }
        __syncthreads();

#pragma unroll
        for (int kk = 0; kk < 16; kk++) {
            float ra[8], rb[8];
#pragma unroll
            for (int i = 0; i < 8; i++) ra[i] = As[kk][ty * 8 + i];
#pragma unroll
            for (int j = 0; j < 8; j++) rb[j] = Bs[kk][tx * 8 + j];
#pragma unroll
            for (int i = 0; i < 8; i++)
#pragma unroll
                for (int j = 0; j < 8; j++) acc[i][j] += ra[i] * rb[j];
        }
        __syncthreads();
    }

#pragma unroll
    for (int i = 0; i < 8; i++) {
        int r = brow * 128 + ty * 8 + i;
        float* dst = g_xp + (size_t)r * H_ + bcol * 128 + tx * 8;
        int colb = bcol * 128 + tx * 8;
#pragma unroll
        for (int j = 0; j < 8; j++)
            dst[j] = acc[i][j] + b_ih[colb + j];
    }
}

// ---------------------------------------------------------------------------
// Classifier GEMM (scalar, tiny)
// ---------------------------------------------------------------------------
__global__ __launch_bounds__(256) void gemm_clf(
    const float* __restrict__ A, const float* __restrict__ W,
    const float* __restrict__ bias, float* __restrict__ C, int N, int K)
{
    __shared__ float As[16][36];
    __shared__ float Bs[16][68];

    const int tid = threadIdx.x;
    const int rowBase = blockIdx.y * 32;
    const int colBase = blockIdx.x * 64;
    const int tr = tid >> 5;
    const int tc = tid & 31;

    float acc[4][2];
#pragma unroll
    for (int i = 0; i < 4; i++) { acc[i][0] = 0.f; acc[i][1] = 0.f; }

    for (int k0 = 0; k0 < K; k0 += 16) {
        if (tid < 128) {
            int m = tid >> 2, q = tid & 3;
            float4 a = *(const float4*)(A + (size_t)(rowBase + m) * K + k0 + q * 4);
            As[q * 4 + 0][m] = a.x; As[q * 4 + 1][m] = a.y;
            As[q * 4 + 2][m] = a.z; As[q * 4 + 3][m] = a.w;
        }
        {
            int n = tid >> 2, q = tid & 3;
            float4 w = *(const float4*)(W + (size_t)(colBase + n) * K + k0 + q * 4);
            Bs[q * 4 + 0][n] = w.x; Bs[q * 4 + 1][n] = w.y;
            Bs[q * 4 + 2][n] = w.z; Bs[q * 4 + 3][n] = w.w;
        }
        __syncthreads();

#pragma unroll
        for (int kk = 0; kk < 16; kk++) {
            float ra[4], rb[2];
#pragma unroll
            for (int i = 0; i < 4; i++) ra[i] = As[kk][tr * 4 + i];
            rb[0] = Bs[kk][tc * 2 + 0];
            rb[1] = Bs[kk][tc * 2 + 1];
#pragma unroll
            for (int i = 0; i < 4; i++) {
                acc[i][0] += ra[i] * rb[0];
                acc[i][1] += ra[i] * rb[1];
            }
        }
        __syncthreads();
    }

#pragma unroll
    for (int i = 0; i < 4; i++) {
        int row = rowBase + tr * 4 + i;
#pragma unroll
        for (int j = 0; j < 2; j++) {
            int col = colBase + tc * 2 + j;
            C[(size_t)row * N + col] = acc[i][j] + bias[col];
        }
    }
}

// ---------------------------------------------------------------------------
// Init kernels
// ---------------------------------------------------------------------------
__global__ void zero_h_kernel() {
    int i = blockIdx.x * blockDim.x + threadIdx.x;
    if (i < B_ * H_) {
        g_h[0][i] = 0.f;
        g_hsplit[0][i] = 0.f;
        g_hsplit[1][i] = 0.f;
    }
}

__global__ void wsplit_kernel(const float* __restrict__ W) {
    int i = blockIdx.x * blockDim.x + threadIdx.x;
    if (i < H_ * H_) {
        int row = i >> 10;
        int col = i & 1023;
        int j = col & 7;
        int p = (col & ~7) | ((j & 3) << 1) | (j >> 2);   // k-pair permutation
        float w = W[i];
        float hi = tf32_rna(w);
        g_wsplit[0][(size_t)row * H_ + p] = hi;
        g_wsplit[1][(size_t)row * H_ + p] = tf32_rna(w - hi);
    }
}

// ---------------------------------------------------------------------------
extern "C" void kernel_launch(void* const* d_in, const int* in_sizes, int n_in,
                              void* d_out, int out_size)
{
    const int*   x     = (const int*)d_in[0];
    const float* emb   = (const float*)d_in[1];
    const float* W_ih  = (const float*)d_in[2];
    const float* b_ih  = (const float*)d_in[3];
    const float* W_hh  = (const float*)d_in[4];
    const float* b_hh  = (const float*)d_in[5];
    const float* W_clf = (const float*)d_in[6];
    const float* b_clf = (const float*)d_in[7];
    float*       out   = (float*)d_out;

    float *xp = nullptr, *hb = nullptr, *hs = nullptr, *ws = nullptr;
    cudaGetSymbolAddress((void**)&xp, g_xp);
    cudaGetSymbolAddress((void**)&hb, g_h);
    cudaGetSymbolAddress((void**)&hs, g_hsplit);
    cudaGetSymbolAddress((void**)&ws, g_wsplit);

    static bool attrSet = false;
    if (!attrSet) {
        cudaFuncSetAttribute(rnn_step_kernel,
                             cudaFuncAttributeMaxDynamicSharedMemorySize, STEP_SMEM);
        attrSet = true;
    }

    // --- init: h0 = 0, split W_hh into permuted hi/lo tf32 planes ---
    zero_h_kernel<<<(B_ * H_ + 255) / 256, 256>>>();
    wsplit_kernel<<<(H_ * H_ + 255) / 256, 256>>>(W_hh);

    // --- xp[s,b,h] = emb[x[b,s]] @ W_ih^T + b_ih ---
    embed_proj_kernel<<<dim3(H_ / 128, (B_ * S_) / 128), 256>>>(x, emb, W_ih, b_ih);

    // --- scan: h_{t+1} = tanh(h_t @ W_hh^T + xp_t + b_hh) ---
    const float* whi = ws;
    const float* wlo = ws + (size_t)H_ * H_;
    for (int s = 0; s < S_; s++) {
        int in_buf = s & 1;
        int out_buf = (s + 1) & 1;
        const float* xpt = xp + (size_t)s * B_ * H_;
        rnn_step_kernel<<<dim3(16, 8), 256, STEP_SMEM>>>(
            hs + (size_t)(in_buf * 2) * B_ * H_,
            hs + (size_t)(in_buf * 2 + 1) * B_ * H_,
            whi, wlo, xpt, b_hh,
            hb + (size_t)out_buf * B_ * H_,
            hs + (size_t)(out_buf * 2) * B_ * H_,
            hs + (size_t)(out_buf * 2 + 1) * B_ * H_);
    }

    // --- classifier: out = h_final @ W_clf^T + b_clf (final in buffer 0) ---
    gemm_clf<<<dim3(O_ / 64, B_ / 32), 256>>>(hb, W_clf, b_clf, out, O_, H_);
}